// round 4
// baseline (speedup 1.0000x reference)
#include <cuda_runtime.h>
#include <cuda_fp16.h>
#include <cstdint>

// ---------------------------------------------------------------------------
// Problem constants
// ---------------------------------------------------------------------------
#define NB        128
#define TT        2048
#define FF        88
#define WIN       64
#define X_ELEMS   (NB*TT*FF)            // 23068672
#define W_ELEMS   (FF*WIN*FF)           // 495616
#define OUT_HALF  23068672              // elements per output copy
#define TILE_T    512                   // t rows per CTA
#define NWARPS    16
#define ROWS_PER_WARP 32                // 2 m16 tiles
#define KPAD      96                    // K per tau padded 88 -> 96 (6 k16 steps)
#define WPITCH    208                   // bytes per W row (96 halfs = 192 + 16 pad)
#define WTAU_BYTES (FF*WPITCH)          // 18304
#define XPITCH    176                   // 88 fp16 bytes per frame
#define WINFRAMES (WIN + TILE_T - 1)    // 575
#define NSTAGES   3

// smem layout
#define S_MBX     16
#define S_MBW     32                    // 3 x 8B
#define S_W       1024                  // 3 stages x 18304
#define S_X       (1024 + NSTAGES*WTAU_BYTES)     // 55936
#define X_BYTES   (WINFRAMES*XPITCH)              // 101200
#define SMEM_ALLOC (S_X + X_BYTES + 64)           // 157264

// ---------------------------------------------------------------------------
// Device scratch (static — no runtime allocation allowed)
// ---------------------------------------------------------------------------
__device__ __align__(1024) unsigned char g_Wimg[WIN * WTAU_BYTES];   // ~1.17 MB
__device__ __align__(16)   __half        g_xh[X_ELEMS];              // 46 MB

// ---------------------------------------------------------------------------
// PTX helpers (base sm_90 features only — NO tcgen05/TMEM)
// ---------------------------------------------------------------------------
__device__ __forceinline__ uint32_t smem_to_u32(const void* p) {
    uint32_t a;
    asm("{ .reg .u64 t; cvta.to.shared.u64 t, %1; cvt.u32.u64 %0, t; }" : "=r"(a) : "l"(p));
    return a;
}

#define MBARRIER_INIT(addr, cnt) \
    asm volatile("mbarrier.init.shared.b64 [%0], %1;" :: "r"((uint32_t)(addr)), "r"((uint32_t)(cnt)) : "memory")

#define MBARRIER_EXPECT_TX(addr, bytes) \
    asm volatile("mbarrier.arrive.expect_tx.shared.b64 _, [%0], %1;" :: "r"((uint32_t)(addr)), "r"((uint32_t)(bytes)) : "memory")

#define MBARRIER_WAIT_PARITY(mbar_smem_addr, phase_parity) do { \
    uint32_t _mbar = (uint32_t)(mbar_smem_addr); \
    uint32_t _parity = (uint32_t)(phase_parity); \
    uint32_t _done; \
    asm volatile("{\n\t.reg .pred p;\n\t" \
        "mbarrier.try_wait.parity.acquire.cta.shared::cta.b64 p, [%1], %2;\n\t" \
        "selp.b32 %0, 1, 0, p;\n\t}" \
        : "=r"(_done) : "r"(_mbar), "r"(_parity) : "memory"); \
    if (!_done) { \
        asm volatile("{\n\t.reg .pred P1;\n\t" \
            "WAIT_LOOP_%=:\n\t" \
            "mbarrier.try_wait.parity.acquire.cta.shared::cta.b64 P1, [%0], %1, 0x989680;\n\t" \
            "@P1 bra.uni WAIT_DONE_%=;\n\t" \
            "bra.uni WAIT_LOOP_%=;\n\t" \
            "WAIT_DONE_%=:\n\t}" \
            :: "r"(_mbar), "r"(_parity) : "memory"); \
    } \
} while(0)

__device__ __forceinline__ void bulk_g2s(uint32_t dst_smem, const void* src,
                                         uint32_t bytes, uint32_t mbar) {
    asm volatile(
        "cp.async.bulk.shared::cta.global.mbarrier::complete_tx::bytes [%0], [%1], %2, [%3];"
        :: "r"(dst_smem), "l"(src), "r"(bytes), "r"(mbar) : "memory");
}

__device__ __forceinline__ void ldmatrix_x4(uint32_t& r0, uint32_t& r1,
                                            uint32_t& r2, uint32_t& r3, uint32_t addr) {
    asm volatile("ldmatrix.sync.aligned.m8n8.x4.shared.b16 {%0,%1,%2,%3}, [%4];"
        : "=r"(r0), "=r"(r1), "=r"(r2), "=r"(r3) : "r"(addr));
}
__device__ __forceinline__ void ldmatrix_x2(uint32_t& r0, uint32_t& r1, uint32_t addr) {
    asm volatile("ldmatrix.sync.aligned.m8n8.x2.shared.b16 {%0,%1}, [%2];"
        : "=r"(r0), "=r"(r1) : "r"(addr));
}

__device__ __forceinline__ void mma16816(float* c, uint32_t a0, uint32_t a1,
                                         uint32_t a2, uint32_t a3,
                                         uint32_t b0, uint32_t b1) {
    asm volatile("mma.sync.aligned.m16n8k16.row.col.f32.f16.f16.f32 "
        "{%0,%1,%2,%3}, {%4,%5,%6,%7}, {%8,%9}, {%0,%1,%2,%3};"
        : "+f"(c[0]), "+f"(c[1]), "+f"(c[2]), "+f"(c[3])
        : "r"(a0), "r"(a1), "r"(a2), "r"(a3), "r"(b0), "r"(b1));
}

// ---------------------------------------------------------------------------
// Prep kernels
// ---------------------------------------------------------------------------
__global__ void prep_x_kernel(const float* __restrict__ x) {
    size_t i = (size_t)blockIdx.x * blockDim.x + threadIdx.x;
    size_t stride = (size_t)gridDim.x * blockDim.x;
    const float4* x4 = (const float4*)x;
    __half2* o = (__half2*)g_xh;
    size_t n4 = X_ELEMS / 4;
    for (; i < n4; i += stride) {
        float4 v = x4[i];
        o[2*i]   = __floats2half2_rn(v.x, v.y);
        o[2*i+1] = __floats2half2_rn(v.z, v.w);
    }
}

// W image: [tau][n][k] with row pitch WPITCH bytes, k padded 88->96 with zeros
__global__ void prep_w_kernel(const float* __restrict__ W) {
    int idx = blockIdx.x * 256 + threadIdx.x;   // 64*88*96 = 540672
    if (idx >= WIN * FF * KPAD) return;
    int k   = idx % KPAD;
    int n   = (idx / KPAD) % FF;
    int tau = idx / (KPAD * FF);
    float v = (k < FF) ? W[(size_t)n * (WIN*FF) + tau * FF + k] : 0.0f;
    *(__half*)(g_Wimg + (size_t)tau * WTAU_BYTES + (size_t)n * WPITCH + (size_t)k * 2)
        = __float2half_rn(v);
}

// ---------------------------------------------------------------------------
// Main kernel: per-CTA 512 rows x 88 cols, K-loop over 64 taus
// ---------------------------------------------------------------------------
__global__ void __launch_bounds__(512, 1)
main_gemm_kernel(const float* __restrict__ bias, float* __restrict__ out) {
    extern __shared__ unsigned char smem[];
    uint32_t sb = smem_to_u32(smem);
    int tid = threadIdx.x;
    int wid = tid >> 5, lane = tid & 31;

    int cta = blockIdx.x;
    int n_b = cta >> 2;               // batch index
    int t0  = (cta & 3) * TILE_T;

    uint32_t mb_x = sb + S_MBX;
    uint32_t mb_w = sb + S_MBW;       // 3 barriers

    if (tid == 0) {
        MBARRIER_INIT(mb_x, 1);
        MBARRIER_INIT(mb_w + 0, 1);
        MBARRIER_INIT(mb_w + 8, 1);
        MBARRIER_INIT(mb_w + 16, 1);
    }
    // zero the 64-byte tail pad of the x window (read by last k-step OOB lanes)
    if (tid < 16) *(uint32_t*)(smem + S_X + X_BYTES + tid*4) = 0u;
    // zero-pad the first 64 frames when t0 == 0
    if (t0 == 0) {
        for (int i = tid; i < WIN*XPITCH/4; i += 512)
            *(uint32_t*)(smem + S_X + i*4) = 0u;
    }
    __syncthreads();

    if (tid == 0) {
        if (t0 == 0) {
            MBARRIER_EXPECT_TX(mb_x, (WINFRAMES-WIN)*XPITCH);
            bulk_g2s(sb + S_X + WIN*XPITCH,
                     (const void*)(g_xh + (size_t)n_b*TT*FF),
                     (WINFRAMES-WIN)*XPITCH, mb_x);
        } else {
            MBARRIER_EXPECT_TX(mb_x, WINFRAMES*XPITCH);
            bulk_g2s(sb + S_X,
                     (const void*)(g_xh + ((size_t)n_b*TT + t0 - WIN)*FF),
                     WINFRAMES*XPITCH, mb_x);
        }
        #pragma unroll
        for (int i = 0; i < NSTAGES; i++) {
            MBARRIER_EXPECT_TX(mb_w + i*8, WTAU_BYTES);
            bulk_g2s(sb + S_W + i*WTAU_BYTES,
                     (const void*)(g_Wimg + (size_t)i*WTAU_BYTES),
                     WTAU_BYTES, mb_w + i*8);
        }
    }
    MBARRIER_WAIT_PARITY(mb_x, 0);

    // per-lane base addresses
    // A (x window): row = wid*32 + mt*16 + (lane&15) + tau; koff16 = (lane>>4)*16
    uint32_t a_base = sb + S_X
        + (uint32_t)(wid*ROWS_PER_WARP + (lane & 15)) * XPITCH
        + ((uint32_t)(lane >> 4) << 4);
    // B (W image): n = (lane&7) + ((lane>>4)&1)*8 + jp*16 ; koff = ((lane>>3)&1)*16
    uint32_t b_lane = (uint32_t)((lane & 7) + ((lane >> 4) & 1) * 8) * WPITCH
        + (uint32_t)((lane >> 3) & 1) * 16;
    // x2 (tile 10): lanes 0-15: n = 80 + (lane&7), koff = ((lane>>3)&1)*16
    uint32_t b_lane2 = (uint32_t)(80 + (lane & 7)) * WPITCH
        + (uint32_t)((lane >> 3) & 1) * 16;

    float acc[2][11][4];
    #pragma unroll
    for (int mt = 0; mt < 2; mt++)
        #pragma unroll
        for (int j = 0; j < 11; j++)
            #pragma unroll
            for (int c = 0; c < 4; c++) acc[mt][j][c] = 0.0f;

    int stage = 0;
    uint32_t wpar = 0;   // per-stage next-wait parity bits

    for (int tau = 0; tau < WIN; tau++) {
        MBARRIER_WAIT_PARITY(mb_w + stage*8, (wpar >> stage) & 1);

        uint32_t wbase = sb + S_W + (uint32_t)stage * WTAU_BYTES;
        uint32_t abase_tau = a_base + (uint32_t)tau * XPITCH;

        #pragma unroll
        for (int kk = 0; kk < 6; kk++) {
            uint32_t a0[4], a1[4];
            ldmatrix_x4(a0[0], a0[1], a0[2], a0[3], abase_tau + kk*32);
            ldmatrix_x4(a1[0], a1[1], a1[2], a1[3], abase_tau + 16*XPITCH + kk*32);
            #pragma unroll
            for (int jp = 0; jp < 5; jp++) {
                uint32_t b0, b1, b2, b3;
                ldmatrix_x4(b0, b1, b2, b3, wbase + b_lane + (uint32_t)jp*16*WPITCH + kk*32);
                mma16816(acc[0][2*jp],   a0[0], a0[1], a0[2], a0[3], b0, b1);
                mma16816(acc[1][2*jp],   a1[0], a1[1], a1[2], a1[3], b0, b1);
                mma16816(acc[0][2*jp+1], a0[0], a0[1], a0[2], a0[3], b2, b3);
                mma16816(acc[1][2*jp+1], a1[0], a1[1], a1[2], a1[3], b2, b3);
            }
            {
                uint32_t b0, b1;
                ldmatrix_x2(b0, b1, wbase + b_lane2 + kk*32);
                mma16816(acc[0][10], a0[0], a0[1], a0[2], a0[3], b0, b1);
                mma16816(acc[1][10], a1[0], a1[1], a1[2], a1[3], b0, b1);
            }
        }

        __syncthreads();
        // reload SAME stage for tau+3 (stage(tau+3) == stage(tau))
        if (tid == 0 && tau + NSTAGES < WIN) {
            MBARRIER_EXPECT_TX(mb_w + stage*8, WTAU_BYTES);
            bulk_g2s(sb + S_W + (uint32_t)stage*WTAU_BYTES,
                     (const void*)(g_Wimg + (size_t)(tau + NSTAGES)*WTAU_BYTES),
                     WTAU_BYTES, mb_w + stage*8);
        }
        wpar ^= (1u << stage);
        stage = (stage == NSTAGES-1) ? 0 : stage + 1;
    }

    // ---- epilogue: add bias, store twice ----
    {
        int col0 = (lane & 3) * 2;          // within n-tile
        int rbase = t0 + wid * ROWS_PER_WARP + (lane >> 2);
        #pragma unroll
        for (int mt = 0; mt < 2; mt++) {
            int r0 = rbase + mt * 16;
            size_t g0 = ((size_t)n_b * TT + r0)     * FF;
            size_t g1 = ((size_t)n_b * TT + r0 + 8) * FF;
            #pragma unroll
            for (int j = 0; j < 11; j++) {
                int c = j * 8 + col0;
                float bx = bias[c], by = bias[c + 1];
                float2 v0 = make_float2(acc[mt][j][0] + bx, acc[mt][j][1] + by);
                float2 v1 = make_float2(acc[mt][j][2] + bx, acc[mt][j][3] + by);
                *(float2*)(out + g0 + c) = v0;
                *(float2*)(out + g1 + c) = v1;
                *(float2*)(out + OUT_HALF + g0 + c) = v0;
                *(float2*)(out + OUT_HALF + g1 + c) = v1;
            }
        }
    }
}

// ---------------------------------------------------------------------------
// Launch
// ---------------------------------------------------------------------------
extern "C" void kernel_launch(void* const* d_in, const int* in_sizes, int n_in,
                              void* d_out, int out_size) {
    const float *x = nullptr, *W = nullptr, *b = nullptr;
    for (int i = 0; i < n_in; i++) {
        if      (in_sizes[i] == X_ELEMS) x = (const float*)d_in[i];
        else if (in_sizes[i] == W_ELEMS) W = (const float*)d_in[i];
        else if (in_sizes[i] == FF)      b = (const float*)d_in[i];
    }
    cudaFuncSetAttribute(main_gemm_kernel,
                         cudaFuncAttributeMaxDynamicSharedMemorySize, SMEM_ALLOC);
    prep_x_kernel<<<2048, 256>>>(x);
    prep_w_kernel<<<(WIN*FF*KPAD + 255)/256, 256>>>(W);
    main_gemm_kernel<<<NB*(TT/TILE_T), 512, SMEM_ALLOC>>>(b, (float*)d_out);
}

// round 6
// speedup vs baseline: 1.1963x; 1.1963x over previous
#include <cuda_runtime.h>
#include <cuda_fp16.h>
#include <cstdint>

// ---------------------------------------------------------------------------
// Problem constants
// ---------------------------------------------------------------------------
#define NB        128
#define TT        2048
#define FF        88
#define WIN       64
#define X_ELEMS   (NB*TT*FF)            // 23068672
#define W_ELEMS   (FF*WIN*FF)           // 495616
#define OUT_HALF  23068672              // elements per output copy
#define TILE_T    256                   // t rows per CTA
#define NWARPS    8
#define ROWS_PER_WARP 32                // 2 m16 tiles
#define KPAD      96                    // K per tau padded 88 -> 96 (6 k16 steps)
#define WPITCH    208                   // bytes per W row (96 halfs = 192 + 16 pad)
#define WTAU_BYTES (FF*WPITCH)          // 18304
#define XPITCH    176                   // 88 fp16 bytes per frame
#define WINFRAMES (WIN + TILE_T - 1)    // 319
#define NSTAGES   3

// smem layout
#define S_MBX     16
#define S_MBW     32                    // 3 x 8B
#define S_W       1024                  // 3 stages x 18304
#define S_X       (1024 + NSTAGES*WTAU_BYTES)     // 55936
#define X_BYTES   (WINFRAMES*XPITCH)              // 56144
#define SMEM_ALLOC (S_X + X_BYTES + 64)           // 112144  (x2 CTAs = 224288 <= 228KB)

// ---------------------------------------------------------------------------
// Device scratch (static — no runtime allocation allowed)
// ---------------------------------------------------------------------------
__device__ __align__(1024) unsigned char g_Wimg[WIN * WTAU_BYTES];   // ~1.17 MB
__device__ __align__(16)   __half        g_xh[X_ELEMS];              // 46 MB

// ---------------------------------------------------------------------------
// PTX helpers (base features only — NO tcgen05/TMEM, target is plain sm_103)
// ---------------------------------------------------------------------------
__device__ __forceinline__ uint32_t smem_to_u32(const void* p) {
    uint32_t a;
    asm("{ .reg .u64 t; cvta.to.shared.u64 t, %1; cvt.u32.u64 %0, t; }" : "=r"(a) : "l"(p));
    return a;
}

#define MBARRIER_INIT(addr, cnt) \
    asm volatile("mbarrier.init.shared.b64 [%0], %1;" :: "r"((uint32_t)(addr)), "r"((uint32_t)(cnt)) : "memory")

#define MBARRIER_EXPECT_TX(addr, bytes) \
    asm volatile("mbarrier.arrive.expect_tx.shared.b64 _, [%0], %1;" :: "r"((uint32_t)(addr)), "r"((uint32_t)(bytes)) : "memory")

#define MBARRIER_WAIT_PARITY(mbar_smem_addr, phase_parity) do { \
    uint32_t _mbar = (uint32_t)(mbar_smem_addr); \
    uint32_t _parity = (uint32_t)(phase_parity); \
    uint32_t _done; \
    asm volatile("{\n\t.reg .pred p;\n\t" \
        "mbarrier.try_wait.parity.acquire.cta.shared::cta.b64 p, [%1], %2;\n\t" \
        "selp.b32 %0, 1, 0, p;\n\t}" \
        : "=r"(_done) : "r"(_mbar), "r"(_parity) : "memory"); \
    if (!_done) { \
        asm volatile("{\n\t.reg .pred P1;\n\t" \
            "WAIT_LOOP_%=:\n\t" \
            "mbarrier.try_wait.parity.acquire.cta.shared::cta.b64 P1, [%0], %1, 0x989680;\n\t" \
            "@P1 bra.uni WAIT_DONE_%=;\n\t" \
            "bra.uni WAIT_LOOP_%=;\n\t" \
            "WAIT_DONE_%=:\n\t}" \
            :: "r"(_mbar), "r"(_parity) : "memory"); \
    } \
} while(0)

__device__ __forceinline__ void bulk_g2s(uint32_t dst_smem, const void* src,
                                         uint32_t bytes, uint32_t mbar) {
    asm volatile(
        "cp.async.bulk.shared::cta.global.mbarrier::complete_tx::bytes [%0], [%1], %2, [%3];"
        :: "r"(dst_smem), "l"(src), "r"(bytes), "r"(mbar) : "memory");
}

__device__ __forceinline__ void ldmatrix_x4(uint32_t& r0, uint32_t& r1,
                                            uint32_t& r2, uint32_t& r3, uint32_t addr) {
    asm volatile("ldmatrix.sync.aligned.m8n8.x4.shared.b16 {%0,%1,%2,%3}, [%4];"
        : "=r"(r0), "=r"(r1), "=r"(r2), "=r"(r3) : "r"(addr));
}
__device__ __forceinline__ void ldmatrix_x2(uint32_t& r0, uint32_t& r1, uint32_t addr) {
    asm volatile("ldmatrix.sync.aligned.m8n8.x2.shared.b16 {%0,%1}, [%2];"
        : "=r"(r0), "=r"(r1) : "r"(addr));
}

__device__ __forceinline__ void mma16816(float* c, uint32_t a0, uint32_t a1,
                                         uint32_t a2, uint32_t a3,
                                         uint32_t b0, uint32_t b1) {
    asm volatile("mma.sync.aligned.m16n8k16.row.col.f32.f16.f16.f32 "
        "{%0,%1,%2,%3}, {%4,%5,%6,%7}, {%8,%9}, {%0,%1,%2,%3};"
        : "+f"(c[0]), "+f"(c[1]), "+f"(c[2]), "+f"(c[3])
        : "r"(a0), "r"(a1), "r"(a2), "r"(a3), "r"(b0), "r"(b1));
}

// ---------------------------------------------------------------------------
// Fused prep kernel: blocks [0,2048) convert x; blocks [2048, ...) build W image
// ---------------------------------------------------------------------------
#define PREP_X_BLOCKS 2048
#define PREP_W_ITEMS  (WIN*FF*KPAD)     // 540672
#define PREP_W_BLOCKS ((PREP_W_ITEMS + 255)/256)

__global__ void prep_kernel(const float* __restrict__ x, const float* __restrict__ W) {
    if (blockIdx.x < PREP_X_BLOCKS) {
        size_t i = (size_t)blockIdx.x * blockDim.x + threadIdx.x;
        size_t stride = (size_t)PREP_X_BLOCKS * blockDim.x;
        const float4* x4 = (const float4*)x;
        __half2* o = (__half2*)g_xh;
        size_t n4 = X_ELEMS / 4;
        for (; i < n4; i += stride) {
            float4 v = x4[i];
            o[2*i]   = __floats2half2_rn(v.x, v.y);
            o[2*i+1] = __floats2half2_rn(v.z, v.w);
        }
    } else {
        int idx = (blockIdx.x - PREP_X_BLOCKS) * 256 + threadIdx.x;
        if (idx >= PREP_W_ITEMS) return;
        int k   = idx % KPAD;
        int n   = (idx / KPAD) % FF;
        int tau = idx / (KPAD * FF);
        float v = (k < FF) ? W[(size_t)n * (WIN*FF) + tau * FF + k] : 0.0f;
        *(__half*)(g_Wimg + (size_t)tau * WTAU_BYTES + (size_t)n * WPITCH + (size_t)k * 2)
            = __float2half_rn(v);
    }
}

// ---------------------------------------------------------------------------
// Main kernel: per-CTA 256 rows x 88 cols, K-loop over 64 taus, occ=2
// ---------------------------------------------------------------------------
__global__ void __launch_bounds__(256, 2)
main_gemm_kernel(const float* __restrict__ bias, float* __restrict__ out) {
    extern __shared__ unsigned char smem[];
    uint32_t sb = smem_to_u32(smem);
    int tid = threadIdx.x;
    int wid = tid >> 5, lane = tid & 31;

    int cta = blockIdx.x;
    int n_b = cta >> 3;               // batch index
    int t0  = (cta & 7) * TILE_T;

    uint32_t mb_x = sb + S_MBX;
    uint32_t mb_w = sb + S_MBW;       // 3 barriers

    if (tid == 0) {
        MBARRIER_INIT(mb_x, 1);
        MBARRIER_INIT(mb_w + 0, 1);
        MBARRIER_INIT(mb_w + 8, 1);
        MBARRIER_INIT(mb_w + 16, 1);
    }
    // zero the 64-byte tail pad of the x window
    if (tid < 16) *(uint32_t*)(smem + S_X + X_BYTES + tid*4) = 0u;
    // zero-pad the first 64 frames when t0 == 0
    if (t0 == 0) {
        for (int i = tid; i < WIN*XPITCH/4; i += 256)
            *(uint32_t*)(smem + S_X + i*4) = 0u;
    }
    __syncthreads();

    if (tid == 0) {
        if (t0 == 0) {
            MBARRIER_EXPECT_TX(mb_x, (WINFRAMES-WIN)*XPITCH);
            bulk_g2s(sb + S_X + WIN*XPITCH,
                     (const void*)(g_xh + (size_t)n_b*TT*FF),
                     (WINFRAMES-WIN)*XPITCH, mb_x);
        } else {
            MBARRIER_EXPECT_TX(mb_x, WINFRAMES*XPITCH);
            bulk_g2s(sb + S_X,
                     (const void*)(g_xh + ((size_t)n_b*TT + t0 - WIN)*FF),
                     WINFRAMES*XPITCH, mb_x);
        }
        #pragma unroll
        for (int i = 0; i < NSTAGES; i++) {
            MBARRIER_EXPECT_TX(mb_w + i*8, WTAU_BYTES);
            bulk_g2s(sb + S_W + i*WTAU_BYTES,
                     (const void*)(g_Wimg + (size_t)i*WTAU_BYTES),
                     WTAU_BYTES, mb_w + i*8);
        }
    }
    MBARRIER_WAIT_PARITY(mb_x, 0);

    // per-lane base addresses
    // A (x window): row = wid*32 + mt*16 + (lane&15) + tau; koff16 = (lane>>4)*16
    uint32_t a_base = sb + S_X
        + (uint32_t)(wid*ROWS_PER_WARP + (lane & 15)) * XPITCH
        + ((uint32_t)(lane >> 4) << 4);
    // B (W image): n = (lane&7) + ((lane>>4)&1)*8 + jp*16 ; koff = ((lane>>3)&1)*16
    uint32_t b_lane = (uint32_t)((lane & 7) + ((lane >> 4) & 1) * 8) * WPITCH
        + (uint32_t)((lane >> 3) & 1) * 16;
    // x2 (tile 10): lanes 0-15: n = 80 + (lane&7), koff = ((lane>>3)&1)*16
    uint32_t b_lane2 = (uint32_t)(80 + (lane & 7)) * WPITCH
        + (uint32_t)((lane >> 3) & 1) * 16;

    float acc[2][11][4];
    #pragma unroll
    for (int mt = 0; mt < 2; mt++)
        #pragma unroll
        for (int j = 0; j < 11; j++)
            #pragma unroll
            for (int c = 0; c < 4; c++) acc[mt][j][c] = 0.0f;

    int stage = 0;
    uint32_t wpar = 0;   // per-stage next-wait parity bits

    for (int tau = 0; tau < WIN; tau++) {
        MBARRIER_WAIT_PARITY(mb_w + stage*8, (wpar >> stage) & 1);

        uint32_t wbase = sb + S_W + (uint32_t)stage * WTAU_BYTES;
        uint32_t abase_tau = a_base + (uint32_t)tau * XPITCH;

        #pragma unroll
        for (int kk = 0; kk < 6; kk++) {
            uint32_t a0[4], a1[4];
            ldmatrix_x4(a0[0], a0[1], a0[2], a0[3], abase_tau + kk*32);
            ldmatrix_x4(a1[0], a1[1], a1[2], a1[3], abase_tau + 16*XPITCH + kk*32);
            #pragma unroll
            for (int jp = 0; jp < 5; jp++) {
                uint32_t b0, b1, b2, b3;
                ldmatrix_x4(b0, b1, b2, b3, wbase + b_lane + (uint32_t)jp*16*WPITCH + kk*32);
                mma16816(acc[0][2*jp],   a0[0], a0[1], a0[2], a0[3], b0, b1);
                mma16816(acc[1][2*jp],   a1[0], a1[1], a1[2], a1[3], b0, b1);
                mma16816(acc[0][2*jp+1], a0[0], a0[1], a0[2], a0[3], b2, b3);
                mma16816(acc[1][2*jp+1], a1[0], a1[1], a1[2], a1[3], b2, b3);
            }
            {
                uint32_t b0, b1;
                ldmatrix_x2(b0, b1, wbase + b_lane2 + kk*32);
                mma16816(acc[0][10], a0[0], a0[1], a0[2], a0[3], b0, b1);
                mma16816(acc[1][10], a1[0], a1[1], a1[2], a1[3], b0, b1);
            }
        }

        __syncthreads();
        // reload SAME stage for tau+3 (stage(tau+3) == stage(tau))
        if (tid == 0 && tau + NSTAGES < WIN) {
            MBARRIER_EXPECT_TX(mb_w + stage*8, WTAU_BYTES);
            bulk_g2s(sb + S_W + (uint32_t)stage*WTAU_BYTES,
                     (const void*)(g_Wimg + (size_t)(tau + NSTAGES)*WTAU_BYTES),
                     WTAU_BYTES, mb_w + stage*8);
        }
        wpar ^= (1u << stage);
        stage = (stage == NSTAGES-1) ? 0 : stage + 1;
    }

    // ---- epilogue: add bias, store twice ----
    {
        int col0 = (lane & 3) * 2;          // within n-tile
        int rbase = t0 + wid * ROWS_PER_WARP + (lane >> 2);
        #pragma unroll
        for (int mt = 0; mt < 2; mt++) {
            int r0 = rbase + mt * 16;
            size_t g0 = ((size_t)n_b * TT + r0)     * FF;
            size_t g1 = ((size_t)n_b * TT + r0 + 8) * FF;
            #pragma unroll
            for (int j = 0; j < 11; j++) {
                int c = j * 8 + col0;
                float bx = bias[c], by = bias[c + 1];
                float2 v0 = make_float2(acc[mt][j][0] + bx, acc[mt][j][1] + by);
                float2 v1 = make_float2(acc[mt][j][2] + bx, acc[mt][j][3] + by);
                *(float2*)(out + g0 + c) = v0;
                *(float2*)(out + g1 + c) = v1;
                *(float2*)(out + OUT_HALF + g0 + c) = v0;
                *(float2*)(out + OUT_HALF + g1 + c) = v1;
            }
        }
    }
}

// ---------------------------------------------------------------------------
// Launch
// ---------------------------------------------------------------------------
extern "C" void kernel_launch(void* const* d_in, const int* in_sizes, int n_in,
                              void* d_out, int out_size) {
    const float *x = nullptr, *W = nullptr, *b = nullptr;
    for (int i = 0; i < n_in; i++) {
        if      (in_sizes[i] == X_ELEMS) x = (const float*)d_in[i];
        else if (in_sizes[i] == W_ELEMS) W = (const float*)d_in[i];
        else if (in_sizes[i] == FF)      b = (const float*)d_in[i];
    }
    cudaFuncSetAttribute(main_gemm_kernel,
                         cudaFuncAttributeMaxDynamicSharedMemorySize, SMEM_ALLOC);
    prep_kernel<<<PREP_X_BLOCKS + PREP_W_BLOCKS, 256>>>(x, W);
    main_gemm_kernel<<<NB*(TT/TILE_T), 256, SMEM_ALLOC>>>(b, (float*)d_out);
}